// round 1
// baseline (speedup 1.0000x reference)
#include <cuda_runtime.h>
#include <math.h>

#define NN 100000
#define EE 300000
#define HIDD 128
#define NH (NN*HIDD)

// ---------------- static scratch (no allocations allowed) ----------------
__device__ float g_h[3*NH];     // current layer input features (t,v,e)
__device__ float g_acc[3*NH];   // layer-1 output accumulator
__device__ float g_GL[NH];      // per-relation src projection
__device__ float g_GR[NH];      // per-relation dst projection
__device__ int   g_off[9*(NN+1)];
__device__ int   g_esrc[9*EE];
__device__ int   g_cnt[NN];
__device__ int   g_bsum[128];

// ---------------- CSR build ----------------
__global__ void k_zero(int* p, int n){
    int i = blockIdx.x*blockDim.x + threadIdx.x;
    if (i < n) p[i] = 0;
}

__global__ void k_hist(const int* __restrict__ ei, int* __restrict__ cnt){
    int e = blockIdx.x*blockDim.x + threadIdx.x;
    if (e < EE) atomicAdd(&cnt[ei[EE + e]], 1);
}

__global__ void k_scan1(const int* __restrict__ cnt, int* __restrict__ off, int* __restrict__ bsum){
    __shared__ int sh[1024];
    int d = blockIdx.x*1024 + threadIdx.x;
    sh[threadIdx.x] = (d < NN) ? cnt[d] : 0;
    __syncthreads();
    for (int s = 1; s < 1024; s <<= 1){
        int t = (threadIdx.x >= s) ? sh[threadIdx.x - s] : 0;
        __syncthreads();
        sh[threadIdx.x] += t;
        __syncthreads();
    }
    if (d < NN) off[d+1] = sh[threadIdx.x];
    if (threadIdx.x == 1023) bsum[blockIdx.x] = sh[1023];
}

__global__ void k_scan2(int* __restrict__ off, const int* __restrict__ bsum){
    __shared__ int pre;
    if (threadIdx.x == 0){
        int s = 0;
        for (int b = 0; b < (int)blockIdx.x; b++) s += bsum[b];
        pre = s;
    }
    __syncthreads();
    int d = blockIdx.x*1024 + threadIdx.x;
    if (d < NN) off[d+1] += pre;
    if (d == 0) off[0] = 0;
}

__global__ void k_initcur(const int* __restrict__ off, int* __restrict__ cur){
    int d = blockIdx.x*blockDim.x + threadIdx.x;
    if (d < NN) cur[d] = off[d];
}

__global__ void k_fill(const int* __restrict__ ei, int* __restrict__ cur, int* __restrict__ esrc){
    int e = blockIdx.x*blockDim.x + threadIdx.x;
    if (e < EE){
        int d = ei[EE + e];
        int pos = atomicAdd(&cur[d], 1);
        esrc[pos] = ei[e];
    }
}

// ---------------- input projection: out = x @ W + b  (x: [N,16], W: [16,128]) ----------------
__global__ void k_inproj(const float* __restrict__ x, const float* __restrict__ W,
                         const float* __restrict__ b, float* __restrict__ out){
    __shared__ float Ws[16*128];
    __shared__ float bs[128];
    int j = threadIdx.x;
    for (int i = j; i < 16*128; i += 128) Ws[i] = W[i];
    bs[j] = b[j];
    __syncthreads();
    int n0 = blockIdx.x * 8;
    #pragma unroll
    for (int r = 0; r < 8; r++){
        int n = n0 + r;
        float a = bs[j];
        #pragma unroll
        for (int k = 0; k < 16; k++) a += x[n*16 + k] * Ws[k*128 + j];
        out[n*HIDD + j] = a;
    }
}

// ---------------- SGEMM: C[M,128] = A[M,128] @ B[128,128] ----------------
__global__ __launch_bounds__(256, 2)
void k_sgemm(const float* __restrict__ A, const float* __restrict__ B,
             float* __restrict__ C, int M){
    __shared__ float As[16][132];
    __shared__ float Bs[16][128];
    int tid  = threadIdx.x;
    int row0 = blockIdx.x * 128;
    int tr = (tid >> 4) << 3;
    int tc = (tid & 15) << 3;
    float acc[8][8];
    #pragma unroll
    for (int i = 0; i < 8; i++)
        #pragma unroll
        for (int j = 0; j < 8; j++) acc[i][j] = 0.f;

    int am = tid >> 1;
    int ak = (tid & 1) << 3;
    int bk = tid >> 4;
    int bn = (tid & 15) << 3;
    const bool aok = (row0 + am) < M;
    const float* Ap = A + (row0 + am)*128 + ak;

    for (int k0 = 0; k0 < 128; k0 += 16){
        float4 a0 = make_float4(0.f,0.f,0.f,0.f), a1 = make_float4(0.f,0.f,0.f,0.f);
        if (aok){
            a0 = *(const float4*)(Ap + k0);
            a1 = *(const float4*)(Ap + k0 + 4);
        }
        As[ak+0][am]=a0.x; As[ak+1][am]=a0.y; As[ak+2][am]=a0.z; As[ak+3][am]=a0.w;
        As[ak+4][am]=a1.x; As[ak+5][am]=a1.y; As[ak+6][am]=a1.z; As[ak+7][am]=a1.w;
        *(float4*)&Bs[bk][bn]     = *(const float4*)&B[(k0+bk)*128 + bn];
        *(float4*)&Bs[bk][bn + 4] = *(const float4*)&B[(k0+bk)*128 + bn + 4];
        __syncthreads();
        #pragma unroll
        for (int k = 0; k < 16; k++){
            float ar[8], br[8];
            #pragma unroll
            for (int i = 0; i < 8; i++) ar[i] = As[k][tr+i];
            #pragma unroll
            for (int j = 0; j < 8; j++) br[j] = Bs[k][tc+j];
            #pragma unroll
            for (int i = 0; i < 8; i++)
                #pragma unroll
                for (int j = 0; j < 8; j++) acc[i][j] += ar[i]*br[j];
        }
        __syncthreads();
    }
    #pragma unroll
    for (int i = 0; i < 8; i++){
        int r = row0 + tr + i;
        if (r < M){
            *(float4*)&C[r*128 + tc]     = make_float4(acc[i][0],acc[i][1],acc[i][2],acc[i][3]);
            *(float4*)&C[r*128 + tc + 4] = make_float4(acc[i][4],acc[i][5],acc[i][6],acc[i][7]);
        }
    }
}

// ---------------- init accumulator with sum of the 3 relation biases ----------------
__global__ void k_initbias(float* __restrict__ acc, const float* __restrict__ b1,
                           const float* __restrict__ b2, const float* __restrict__ b3){
    int i = blockIdx.x*blockDim.x + threadIdx.x;   // over NN*32 float4s
    if (i < NN*32){
        int c = (i & 31) * 4;
        float4 v;
        v.x = b1[c+0]+b2[c+0]+b3[c+0];
        v.y = b1[c+1]+b2[c+1]+b3[c+1];
        v.z = b1[c+2]+b2[c+2]+b3[c+2];
        v.w = b1[c+3]+b2[c+3]+b3[c+3];
        ((float4*)acc)[i] = v;
    }
}

// ---------------- GATv2 edge aggregation: one warp per dst node, online softmax ----------------
__global__ __launch_bounds__(256)
void k_gat(const int* __restrict__ off, const int* __restrict__ esrc,
           const float* __restrict__ GL, const float* __restrict__ GR,
           const float* __restrict__ att, float* __restrict__ out){
    int w    = (blockIdx.x*blockDim.x + threadIdx.x) >> 5;
    int lane = threadIdx.x & 31;
    if (w >= NN) return;
    int beg = off[w], end = off[w+1];
    float4 gr = *(const float4*)&GR[w*HIDD + lane*4];   // lanes 0-15: head0, 16-31: head1
    float4 at = ((const float4*)att)[lane];
    float m = -INFINITY, den = 0.f;
    float4 acc = make_float4(0.f,0.f,0.f,0.f);
    for (int k = beg; k < end; k++){
        int s = esrc[k];
        float4 gl = *(const float4*)&GL[s*HIDD + lane*4];
        float sx = gl.x + gr.x, sy = gl.y + gr.y, sz = gl.z + gr.z, sw = gl.w + gr.w;
        sx = sx > 0.f ? sx : 0.2f*sx;
        sy = sy > 0.f ? sy : 0.2f*sy;
        sz = sz > 0.f ? sz : 0.2f*sz;
        sw = sw > 0.f ? sw : 0.2f*sw;
        float e = at.x*sx + at.y*sy + at.z*sz + at.w*sw;
        e += __shfl_xor_sync(0xffffffffu, e, 1);
        e += __shfl_xor_sync(0xffffffffu, e, 2);
        e += __shfl_xor_sync(0xffffffffu, e, 4);
        e += __shfl_xor_sync(0xffffffffu, e, 8);   // per-head score, same within each half-warp
        float mn = fmaxf(m, e);
        float cs = __expf(m - mn);
        float p  = __expf(e - mn);
        den = den*cs + p;
        acc.x = acc.x*cs + p*gl.x;
        acc.y = acc.y*cs + p*gl.y;
        acc.z = acc.z*cs + p*gl.z;
        acc.w = acc.w*cs + p*gl.w;
        m = mn;
    }
    float inv = 1.f / (den + 1e-16f);
    float4* o4 = (float4*)&out[w*HIDD + lane*4];
    float4 o = *o4;
    o.x += acc.x*inv; o.y += acc.y*inv; o.z += acc.z*inv; o.w += acc.w*inv;
    *o4 = o;
}

// ---------------- relu: h = relu(acc) ----------------
__global__ void k_relu(const float* __restrict__ in, float* __restrict__ out, int n4){
    int i = blockIdx.x*blockDim.x + threadIdx.x;
    if (i < n4){
        float4 v = ((const float4*)in)[i];
        v.x = fmaxf(v.x, 0.f); v.y = fmaxf(v.y, 0.f);
        v.z = fmaxf(v.z, 0.f); v.w = fmaxf(v.w, 0.f);
        ((float4*)out)[i] = v;
    }
}

// ---------------- launch ----------------
extern "C" void kernel_launch(void* const* d_in, const int* in_sizes, int n_in,
                              void* d_out, int out_size){
    const float* xt = (const float*)d_in[0];
    const float* xv = (const float*)d_in[1];
    const float* xe = (const float*)d_in[2];
    const float* Wt = (const float*)d_in[12];
    const float* bt = (const float*)d_in[13];
    const float* Wv = (const float*)d_in[14];
    const float* bv = (const float*)d_in[15];
    const float* We = (const float*)d_in[16];
    const float* be = (const float*)d_in[17];

    float *h, *acc, *GL, *GR;
    int *off, *esrc, *cnt, *bsum;
    cudaGetSymbolAddress((void**)&h,    g_h);
    cudaGetSymbolAddress((void**)&acc,  g_acc);
    cudaGetSymbolAddress((void**)&GL,   g_GL);
    cudaGetSymbolAddress((void**)&GR,   g_GR);
    cudaGetSymbolAddress((void**)&off,  g_off);
    cudaGetSymbolAddress((void**)&esrc, g_esrc);
    cudaGetSymbolAddress((void**)&cnt,  g_cnt);
    cudaGetSymbolAddress((void**)&bsum, g_bsum);

    static const int srct[9] = {0,0,1,0,2,1,2,1,2};
    static const int dstt[9] = {0,1,0,2,0,2,1,1,2};

    // ---- build dst-CSR per relation (reused by both layers) ----
    for (int r = 0; r < 9; r++){
        const int* ei = (const int*)d_in[3 + r];
        int* offr = off + r*(NN+1);
        int* esr  = esrc + r*EE;
        k_zero   <<<(NN+255)/256, 256>>>(cnt, NN);
        k_hist   <<<(EE+255)/256, 256>>>(ei, cnt);
        k_scan1  <<<(NN+1023)/1024, 1024>>>(cnt, offr, bsum);
        k_scan2  <<<(NN+1023)/1024, 1024>>>(offr, bsum);
        k_initcur<<<(NN+255)/256, 256>>>(offr, cnt);
        k_fill   <<<(EE+255)/256, 256>>>(ei, cnt, esr);
    }

    // ---- input projections ----
    k_inproj<<<NN/8, 128>>>(xt, Wt, bt, h);
    k_inproj<<<NN/8, 128>>>(xv, Wv, bv, h + NH);
    k_inproj<<<NN/8, 128>>>(xe, We, be, h + 2*NH);

    float* outF = (float*)d_out;
    for (int l = 0; l < 2; l++){
        const float* Wl = (const float*)d_in[18 + l*4];
        const float* Wr = (const float*)d_in[19 + l*4];
        const float* at = (const float*)d_in[20 + l*4];
        const float* bc = (const float*)d_in[21 + l*4];
        float* accB[3];
        if (l == 0){ accB[0] = acc;  accB[1] = acc + NH;  accB[2] = acc + 2*NH; }
        else       { accB[0] = outF; accB[1] = outF + NH; accB[2] = outF + 2*NH; }

        // dst groups: t:{0,2,4}  v:{1,6,7}  e:{3,5,8}
        k_initbias<<<12500, 256>>>(accB[0], bc + 0*128, bc + 2*128, bc + 4*128);
        k_initbias<<<12500, 256>>>(accB[1], bc + 1*128, bc + 6*128, bc + 7*128);
        k_initbias<<<12500, 256>>>(accB[2], bc + 3*128, bc + 5*128, bc + 8*128);

        for (int r = 0; r < 9; r++){
            k_sgemm<<<(NN+127)/128, 256>>>(h + srct[r]*NH, Wl + r*16384, GL, NN);
            k_sgemm<<<(NN+127)/128, 256>>>(h + dstt[r]*NH, Wr + r*16384, GR, NN);
            k_gat  <<<NN/8, 256>>>(off + r*(NN+1), esrc + r*EE, GL, GR, at + r*128, accB[dstt[r]]);
        }
        if (l == 0) k_relu<<<(3*NH/4 + 255)/256, 256>>>(acc, h, 3*NH/4);
    }
}